// round 1
// baseline (speedup 1.0000x reference)
#include <cuda_runtime.h>

#define N_NODES 10000
#define N_EDGES 160000
#define NB 2
#define NT 12
#define NF 16
#define HG 32
#define H 64
#define G 256   /* 4H */
#define NP 4
#define NSEQ 20000
#define NSEQ_PAD 20032
#define BT 24

#define BM 64
#define SP 68
#define K1 96
#define SMEM_FLOATS (24576 + 16384 + 256*3 + 512 + 8 + 96*SP + 64*SP + 768)

// -------- device scratch (zero-initialized at load; pad region never written) --------
__device__ float g_xw[BT * N_NODES * HG];          // [bt][n][hg]
__device__ float g_seq[NSEQ_PAD * NT * HG];        // [seq][t][hg]  (gcn_seq layout)
__device__ int   g_deg[N_NODES];
__device__ int   g_rowptr[N_NODES + 1];
__device__ int   g_cursor[N_NODES];
__device__ int   g_csrc[N_EDGES];
__device__ float g_dinv[N_NODES];

// ---------------- GCN: CSR build ----------------
__global__ void k_initdeg() {
    int i = blockIdx.x * blockDim.x + threadIdx.x;
    if (i < N_NODES) g_deg[i] = 0;
}

__global__ void k_degcount(const int* __restrict__ ei) {
    int e = blockIdx.x * blockDim.x + threadIdx.x;
    if (e < N_EDGES) atomicAdd(&g_deg[ei[N_EDGES + e]], 1);
}

__global__ void k_scan() {
    __shared__ int part[1024];
    const int CH = 10;  // 1024*10 >= 10000
    int tid = threadIdx.x;
    int base = tid * CH;
    int loc[CH];
    int s = 0;
#pragma unroll
    for (int j = 0; j < CH; ++j) {
        int idx = base + j;
        int v = (idx < N_NODES) ? g_deg[idx] : 0;
        loc[j] = s; s += v;
    }
    part[tid] = s;
    __syncthreads();
    for (int off = 1; off < 1024; off <<= 1) {
        int v = (tid >= off) ? part[tid - off] : 0;
        __syncthreads();
        part[tid] += v;
        __syncthreads();
    }
    int boff = (tid > 0) ? part[tid - 1] : 0;
#pragma unroll
    for (int j = 0; j < CH; ++j) {
        int idx = base + j;
        if (idx < N_NODES) {
            int rp = boff + loc[j];
            g_rowptr[idx] = rp;
            g_cursor[idx] = rp;
            g_dinv[idx]   = rsqrtf((float)(g_deg[idx] + 1));  // +1 self loop
        }
    }
    if (tid == 1023) g_rowptr[N_NODES] = part[1023];
}

__global__ void k_fill(const int* __restrict__ ei) {
    int e = blockIdx.x * blockDim.x + threadIdx.x;
    if (e < N_EDGES) {
        int d = ei[N_EDGES + e];
        int p = atomicAdd(&g_cursor[d], 1);
        g_csrc[p] = ei[e];
    }
}

// ---------------- GCN: x @ W ----------------
__global__ void k_xw(const float* __restrict__ x, const float* __restrict__ w) {
    __shared__ float ws[NF * HG];
    for (int i = threadIdx.x; i < NF * HG; i += blockDim.x) ws[i] = w[i];
    __syncthreads();
    int idx = blockIdx.x * blockDim.x + threadIdx.x;
    if (idx >= BT * N_NODES * HG) return;
    int row = idx >> 5;
    int c = idx & 31;
    const float* xr = x + (size_t)row * NF;
    float s = 0.f;
#pragma unroll
    for (int f = 0; f < NF; ++f) s = fmaf(__ldg(&xr[f]), ws[f * HG + c], s);
    g_xw[idx] = s;
}

// ---------------- GCN: per-node gather over in-edges, all 24 (b,t) slices ----------------
__global__ void k_gather(const float* __restrict__ gcn_b) {
    int gw = (blockIdx.x * blockDim.x + threadIdx.x) >> 5;
    int c = threadIdx.x & 31;
    if (gw >= N_NODES) return;
    int n = gw;
    float dn = g_dinv[n];
    float acc[BT];
#pragma unroll
    for (int bt = 0; bt < BT; ++bt)
        acc[bt] = dn * g_xw[(size_t)(bt * N_NODES + n) * HG + c];
    int e0 = g_rowptr[n], e1 = g_rowptr[n + 1];
    for (int e = e0; e < e1; ++e) {
        int s = g_csrc[e];
        float ds = g_dinv[s];
        const float* xp = g_xw + (size_t)s * HG + c;
#pragma unroll
        for (int bt = 0; bt < BT; ++bt)
            acc[bt] = fmaf(ds, xp[(size_t)bt * N_NODES * HG], acc[bt]);
    }
    float bc = gcn_b[c];
#pragma unroll
    for (int bt = 0; bt < BT; ++bt) {
        int b = bt / NT, t = bt % NT;
        g_seq[((size_t)(b * N_NODES + n) * NT + t) * HG + c] = fmaf(dn, acc[bt], bc);
    }
}

// ---------------- fused LSTM1 + LSTM2 + FC ----------------
__device__ __forceinline__ float sigf(float x) {
    float e = __expf(-x);
    return __fdividef(1.f, 1.f + e);
}
__device__ __forceinline__ float tanh_f(float x) {
    float e = __expf(-2.f * fabsf(x));
    float r = __fdividef(1.f - e, 1.f + e);
    return copysignf(r, x);
}

__global__ void __launch_bounds__(256, 1)
k_lstm(const float* __restrict__ zeta,
       const float* __restrict__ w_ih1, const float* __restrict__ w_hh1,
       const float* __restrict__ b_ih1, const float* __restrict__ b_hh1,
       const float* __restrict__ w_ih2, const float* __restrict__ w_hh2,
       const float* __restrict__ b_ih2, const float* __restrict__ b_hh2,
       const float* __restrict__ fc_w, const float* __restrict__ fc_b,
       float* __restrict__ out) {
    extern __shared__ float smf[];
    float* w1    = smf;                 // [96][256]  (rows 0..63 = w_hh1^T, 64..95 = w_ih1^T)
    float* w2    = w1 + K1 * G;         // [64][256]  (w_hh2^T)
    float* bias1 = w2 + H * G;          // 256
    float* bias2 = bias1 + G;           // 256
    float* wz    = bias2 + G;           // 256  (w_ih2 column)
    float* fcw   = wz + G;              // 512
    float* fcb   = fcw + 512;           // 8 (padded)
    float* state = fcb + 8;             // [96][SP]  rows 0..63 = h (transposed [k][m]), 64..95 = x_t
    float* hf1   = state + K1 * SP;     // [64][SP]  saved spatial h
    float* zs    = hf1 + H * SP;        // [64][12]

    int tid = threadIdx.x;
    int tg = tid & 31, tm = tid >> 5;
    int seq0 = blockIdx.x * BM;

    // ---- load weights transposed into smem ----
    for (int i = tid; i < K1 * G; i += 256) {
        int k = i >> 8, g = i & 255;
        w1[i] = (k < H) ? w_hh1[g * H + k] : w_ih1[g * HG + (k - H)];
    }
    for (int i = tid; i < H * G; i += 256) {
        int k = i >> 8, g = i & 255;
        w2[i] = w_hh2[g * H + k];
    }
    if (tid < G) {
        bias1[tid] = b_ih1[tid] + b_hh1[tid];
        bias2[tid] = b_ih2[tid] + b_hh2[tid];
        wz[tid]    = w_ih2[tid];
    }
    for (int i = tid; i < 512; i += 256) fcw[i] = fc_w[i];
    if (tid < NP) fcb[tid] = fc_b[tid];
    // zeta per sequence: zs[m][t]
    for (int i = tid; i < BM * NT; i += 256) {
        int t = i / BM, m = i % BM;
        int seq = seq0 + m;
        float z = 0.f;
        if (seq < NSEQ) {
            int b = seq / N_NODES, n = seq - b * N_NODES;
            z = zeta[(size_t)(b * NT + t) * N_NODES + n];
        }
        zs[m * NT + t] = z;
    }
    // zero h region
    for (int i = tid; i < H * SP; i += 256) state[i] = 0.f;
    __syncthreads();

    float bb1[8];
#pragma unroll
    for (int q = 0; q < 4; ++q) {
        float2 b2 = *(const float2*)&bias1[64 * q + 2 * tg];
        bb1[2 * q] = b2.x; bb1[2 * q + 1] = b2.y;
    }

    float c1[8][2];
#pragma unroll
    for (int im = 0; im < 8; ++im) { c1[im][0] = 0.f; c1[im][1] = 0.f; }

    // ======== LSTM 1 (K = 96: h(64) concat x_t(32)) ========
    for (int t = 0; t < NT; ++t) {
        {   // stage x_t into state rows 64..95 (transposed [kx][m])
            int kx = tid & 31;
            int m0 = tid >> 5;
#pragma unroll
            for (int j = 0; j < 8; ++j) {
                int m = m0 + 8 * j;
                state[(H + kx) * SP + m] =
                    g_seq[(size_t)(seq0 + m) * (NT * HG) + t * HG + kx];
            }
        }
        __syncthreads();
        float acc[8][8];
#pragma unroll
        for (int im = 0; im < 8; ++im)
#pragma unroll
            for (int j = 0; j < 8; ++j) acc[im][j] = bb1[j];

#pragma unroll 4
        for (int k = 0; k < K1; ++k) {
            const float* srow = state + k * SP + 8 * tm;
            float4 h0 = *(const float4*)(srow);
            float4 h1 = *(const float4*)(srow + 4);
            const float* wr = w1 + (k << 8) + 2 * tg;
            float2 wa = *(const float2*)(wr);
            float2 wb = *(const float2*)(wr + 64);
            float2 wc = *(const float2*)(wr + 128);
            float2 wd = *(const float2*)(wr + 192);
            float hv[8] = {h0.x, h0.y, h0.z, h0.w, h1.x, h1.y, h1.z, h1.w};
#pragma unroll
            for (int im = 0; im < 8; ++im) {
                acc[im][0] = fmaf(hv[im], wa.x, acc[im][0]);
                acc[im][1] = fmaf(hv[im], wa.y, acc[im][1]);
                acc[im][2] = fmaf(hv[im], wb.x, acc[im][2]);
                acc[im][3] = fmaf(hv[im], wb.y, acc[im][3]);
                acc[im][4] = fmaf(hv[im], wc.x, acc[im][4]);
                acc[im][5] = fmaf(hv[im], wc.y, acc[im][5]);
                acc[im][6] = fmaf(hv[im], wd.x, acc[im][6]);
                acc[im][7] = fmaf(hv[im], wd.y, acc[im][7]);
            }
        }
        __syncthreads();
#pragma unroll
        for (int im = 0; im < 8; ++im) {
#pragma unroll
            for (int r = 0; r < 2; ++r) {
                float ig = sigf(acc[im][0 + r]);
                float fg = sigf(acc[im][2 + r]);
                float gg = tanh_f(acc[im][4 + r]);
                float og = sigf(acc[im][6 + r]);
                float c = fmaf(fg, c1[im][r], ig * gg);
                c1[im][r] = c;
                state[(2 * tg + r) * SP + 8 * tm + im] = og * tanh_f(c);
            }
        }
        __syncthreads();
    }

    // save spatial h, reset state h for LSTM2
    for (int i = tid; i < H * BM; i += 256) {
        int k = i >> 6, m = i & 63;
        hf1[k * SP + m] = state[k * SP + m];
        state[k * SP + m] = 0.f;
    }
    __syncthreads();

    float bb2[8], wz8[8];
#pragma unroll
    for (int q = 0; q < 4; ++q) {
        float2 b2 = *(const float2*)&bias2[64 * q + 2 * tg];
        bb2[2 * q] = b2.x; bb2[2 * q + 1] = b2.y;
        float2 wv = *(const float2*)&wz[64 * q + 2 * tg];
        wz8[2 * q] = wv.x; wz8[2 * q + 1] = wv.y;
    }
    float c2[8][2];
#pragma unroll
    for (int im = 0; im < 8; ++im) { c2[im][0] = 0.f; c2[im][1] = 0.f; }

    // ======== LSTM 2 (K = 64, scalar input folded into bias) ========
    for (int t = 0; t < NT; ++t) {
        float acc[8][8];
#pragma unroll
        for (int im = 0; im < 8; ++im) {
            float zm = zs[(8 * tm + im) * NT + t];
#pragma unroll
            for (int j = 0; j < 8; ++j) acc[im][j] = fmaf(zm, wz8[j], bb2[j]);
        }
#pragma unroll 4
        for (int k = 0; k < H; ++k) {
            const float* srow = state + k * SP + 8 * tm;
            float4 h0 = *(const float4*)(srow);
            float4 h1 = *(const float4*)(srow + 4);
            const float* wr = w2 + (k << 8) + 2 * tg;
            float2 wa = *(const float2*)(wr);
            float2 wb = *(const float2*)(wr + 64);
            float2 wc = *(const float2*)(wr + 128);
            float2 wd = *(const float2*)(wr + 192);
            float hv[8] = {h0.x, h0.y, h0.z, h0.w, h1.x, h1.y, h1.z, h1.w};
#pragma unroll
            for (int im = 0; im < 8; ++im) {
                acc[im][0] = fmaf(hv[im], wa.x, acc[im][0]);
                acc[im][1] = fmaf(hv[im], wa.y, acc[im][1]);
                acc[im][2] = fmaf(hv[im], wb.x, acc[im][2]);
                acc[im][3] = fmaf(hv[im], wb.y, acc[im][3]);
                acc[im][4] = fmaf(hv[im], wc.x, acc[im][4]);
                acc[im][5] = fmaf(hv[im], wc.y, acc[im][5]);
                acc[im][6] = fmaf(hv[im], wd.x, acc[im][6]);
                acc[im][7] = fmaf(hv[im], wd.y, acc[im][7]);
            }
        }
        __syncthreads();
#pragma unroll
        for (int im = 0; im < 8; ++im) {
#pragma unroll
            for (int r = 0; r < 2; ++r) {
                float ig = sigf(acc[im][0 + r]);
                float fg = sigf(acc[im][2 + r]);
                float gg = tanh_f(acc[im][4 + r]);
                float og = sigf(acc[im][6 + r]);
                float c = fmaf(fg, c2[im][r], ig * gg);
                c2[im][r] = c;
                state[(2 * tg + r) * SP + 8 * tm + im] = og * tanh_f(c);
            }
        }
        __syncthreads();
    }

    // ======== FC + transposed output write ========
    {
        int m = tid & 63;
        int p = tid >> 6;
        float s = fcb[p];
#pragma unroll 8
        for (int k = 0; k < H; ++k) s = fmaf(hf1[k * SP + m], fcw[p * 128 + k], s);
#pragma unroll 8
        for (int k = 0; k < H; ++k) s = fmaf(state[k * SP + m], fcw[p * 128 + H + k], s);
        int seq = seq0 + m;
        if (seq < NSEQ) {
            int b = seq / N_NODES, n = seq - b * N_NODES;
            out[(size_t)(b * NP + p) * N_NODES + n] = s;
        }
    }
}

extern "C" void kernel_launch(void* const* d_in, const int* in_sizes, int n_in,
                              void* d_out, int out_size) {
    const float* era5  = (const float*)d_in[0];
    const float* zeta  = (const float*)d_in[1];
    const int*   ei    = (const int*)d_in[2];
    const float* gcn_w = (const float*)d_in[3];
    const float* gcn_b = (const float*)d_in[4];
    const float* w_ih1 = (const float*)d_in[5];
    const float* w_hh1 = (const float*)d_in[6];
    const float* b_ih1 = (const float*)d_in[7];
    const float* b_hh1 = (const float*)d_in[8];
    const float* w_ih2 = (const float*)d_in[9];
    const float* w_hh2 = (const float*)d_in[10];
    const float* b_ih2 = (const float*)d_in[11];
    const float* b_hh2 = (const float*)d_in[12];
    const float* fc_w  = (const float*)d_in[13];
    const float* fc_b  = (const float*)d_in[14];
    float* out = (float*)d_out;

    k_initdeg<<<(N_NODES + 255) / 256, 256>>>();
    k_degcount<<<(N_EDGES + 255) / 256, 256>>>(ei);
    k_scan<<<1, 1024>>>();
    k_fill<<<(N_EDGES + 255) / 256, 256>>>(ei);
    k_xw<<<(BT * N_NODES * HG + 255) / 256, 256>>>(era5, gcn_w);
    k_gather<<<(N_NODES * 32 + 255) / 256, 256>>>(gcn_b);

    size_t smem = (size_t)SMEM_FLOATS * sizeof(float);
    cudaFuncSetAttribute(k_lstm, cudaFuncAttributeMaxDynamicSharedMemorySize, (int)smem);
    k_lstm<<<(NSEQ + BM - 1) / BM, 256, smem>>>(
        zeta, w_ih1, w_hh1, b_ih1, b_hh1,
        w_ih2, w_hh2, b_ih2, b_hh2, fc_w, fc_b, out);
}

// round 2
// speedup vs baseline: 1.2492x; 1.2492x over previous
#include <cuda_runtime.h>

#define N_NODES 10000
#define N_EDGES 160000
#define NB 2
#define NT 12
#define NF 16
#define HG 32
#define H 64
#define G 256   /* 4H */
#define NP 4
#define NSEQ 20000
#define NSEQ_PAD 20160
#define BT 24

#define BM 136
#define NTHR 544
#define SP 148
#define K1 96

// smem layout (floats)
#define OFF_WBUF  0
#define OFF_B1    24576
#define OFF_B2    24832
#define OFF_WZ    25088
#define OFF_FCW   25344
#define OFF_FCB   25856
#define OFF_ZS    25864            /* 136*12 = 1632 */
#define OFF_Y1    27496            /* 544 */
#define OFF_STATE 28040            /* 96*148 = 14208 */
#define SMEM_FLOATS (OFF_STATE + K1 * SP)

typedef unsigned long long ull;

__device__ __forceinline__ void fma2(ull& d, ull a, ull b) {
    asm("fma.rn.f32x2 %0, %1, %2, %0;" : "+l"(d) : "l"(a), "l"(b));
}
__device__ __forceinline__ ull dup2(float v) {
    ull r; unsigned u = __float_as_uint(v);
    asm("mov.b64 %0, {%1, %1};" : "=l"(r) : "r"(u));
    return r;
}
__device__ __forceinline__ void unpk(float& lo, float& hi, ull v) {
    unsigned a, b;
    asm("mov.b64 {%0, %1}, %2;" : "=r"(a), "=r"(b) : "l"(v));
    lo = __uint_as_float(a); hi = __uint_as_float(b);
}

// -------- device scratch (zero-initialized; pad region stays zero) --------
__device__ float g_xw[BT * N_NODES * HG];
__device__ float g_seq[NSEQ_PAD * NT * HG];
__device__ int   g_deg[N_NODES];
__device__ int   g_rowptr[N_NODES + 1];
__device__ int   g_cursor[N_NODES];
__device__ int   g_csrc[N_EDGES];
__device__ float g_dinv[N_NODES];

// ---------------- GCN: CSR build ----------------
__global__ void k_initdeg() {
    int i = blockIdx.x * blockDim.x + threadIdx.x;
    if (i < N_NODES) g_deg[i] = 0;
}

__global__ void k_degcount(const int* __restrict__ ei) {
    int e = blockIdx.x * blockDim.x + threadIdx.x;
    if (e < N_EDGES) atomicAdd(&g_deg[ei[N_EDGES + e]], 1);
}

__global__ void k_scan() {
    __shared__ int part[1024];
    const int CH = 10;
    int tid = threadIdx.x;
    int base = tid * CH;
    int loc[CH];
    int s = 0;
#pragma unroll
    for (int j = 0; j < CH; ++j) {
        int idx = base + j;
        int v = (idx < N_NODES) ? g_deg[idx] : 0;
        loc[j] = s; s += v;
    }
    part[tid] = s;
    __syncthreads();
    for (int off = 1; off < 1024; off <<= 1) {
        int v = (tid >= off) ? part[tid - off] : 0;
        __syncthreads();
        part[tid] += v;
        __syncthreads();
    }
    int boff = (tid > 0) ? part[tid - 1] : 0;
#pragma unroll
    for (int j = 0; j < CH; ++j) {
        int idx = base + j;
        if (idx < N_NODES) {
            int rp = boff + loc[j];
            g_rowptr[idx] = rp;
            g_cursor[idx] = rp;
            g_dinv[idx]   = rsqrtf((float)(g_deg[idx] + 1));
        }
    }
    if (tid == 1023) g_rowptr[N_NODES] = part[1023];
}

__global__ void k_fill(const int* __restrict__ ei) {
    int e = blockIdx.x * blockDim.x + threadIdx.x;
    if (e < N_EDGES) {
        int d = ei[N_EDGES + e];
        int p = atomicAdd(&g_cursor[d], 1);
        g_csrc[p] = ei[e];
    }
}

// ---------------- GCN: x @ W ----------------
__global__ void k_xw(const float* __restrict__ x, const float* __restrict__ w) {
    __shared__ float ws[NF * HG];
    for (int i = threadIdx.x; i < NF * HG; i += blockDim.x) ws[i] = w[i];
    __syncthreads();
    int idx = blockIdx.x * blockDim.x + threadIdx.x;
    if (idx >= BT * N_NODES * HG) return;
    int row = idx >> 5;
    int c = idx & 31;
    const float* xr = x + (size_t)row * NF;
    float s = 0.f;
#pragma unroll
    for (int f = 0; f < NF; ++f) s = fmaf(__ldg(&xr[f]), ws[f * HG + c], s);
    g_xw[idx] = s;
}

// ---------------- GCN: per-node gather ----------------
__global__ void k_gather(const float* __restrict__ gcn_b) {
    int gw = (blockIdx.x * blockDim.x + threadIdx.x) >> 5;
    int c = threadIdx.x & 31;
    if (gw >= N_NODES) return;
    int n = gw;
    float dn = g_dinv[n];
    float acc[BT];
#pragma unroll
    for (int bt = 0; bt < BT; ++bt)
        acc[bt] = dn * g_xw[(size_t)(bt * N_NODES + n) * HG + c];
    int e0 = g_rowptr[n], e1 = g_rowptr[n + 1];
    for (int e = e0; e < e1; ++e) {
        int s = g_csrc[e];
        float ds = g_dinv[s];
        const float* xp = g_xw + (size_t)s * HG + c;
#pragma unroll
        for (int bt = 0; bt < BT; ++bt)
            acc[bt] = fmaf(ds, xp[(size_t)bt * N_NODES * HG], acc[bt]);
    }
    float bc = gcn_b[c];
#pragma unroll
    for (int bt = 0; bt < BT; ++bt) {
        int b = bt / NT, t = bt % NT;
        g_seq[((size_t)(b * N_NODES + n) * NT + t) * HG + c] = fmaf(dn, acc[bt], bc);
    }
}

// ---------------- fused LSTM1 + LSTM2 + FC ----------------
__device__ __forceinline__ float sigf(float x) {
    float e = __expf(-x);
    return __fdividef(1.f, 1.f + e);
}
__device__ __forceinline__ float tanh_f(float x) {
    float e = __expf(-2.f * fabsf(x));
    float r = __fdividef(1.f - e, 1.f + e);
    return copysignf(r, x);
}

__global__ void __launch_bounds__(NTHR, 1)
k_lstm(const float* __restrict__ zeta,
       const float* __restrict__ w_ih1, const float* __restrict__ w_hh1,
       const float* __restrict__ b_ih1, const float* __restrict__ b_hh1,
       const float* __restrict__ w_ih2, const float* __restrict__ w_hh2,
       const float* __restrict__ b_ih2, const float* __restrict__ b_hh2,
       const float* __restrict__ fc_w, const float* __restrict__ fc_b,
       float* __restrict__ out) {
    extern __shared__ float smf[];
    float* wbuf  = smf + OFF_WBUF;    // [96][256]  w1: rows 0..63 w_hh1^T, 64..95 w_ih1^T; later rows 0..63 = w_hh2^T
    float* bias1 = smf + OFF_B1;
    float* bias2 = smf + OFF_B2;
    float* wz    = smf + OFF_WZ;
    float* fcw   = smf + OFF_FCW;
    float* fcb   = smf + OFF_FCB;
    float* zs    = smf + OFF_ZS;      // [136][12]
    float* y1    = smf + OFF_Y1;      // [4][136]
    float* state = smf + OFF_STATE;   // [96][SP]: rows 0..63 h (k-major), 64..95 x_t

    int tid = threadIdx.x;
    int tg = tid & 31, tm = tid >> 5;           // tm in [0,17)
    int seq0 = blockIdx.x * BM;

    // ---- load weights transposed ----
    for (int i = tid; i < K1 * G; i += NTHR) {
        int k = i >> 8, g = i & 255;
        wbuf[i] = (k < H) ? w_hh1[g * H + k] : w_ih1[g * HG + (k - H)];
    }
    if (tid < G) {
        bias1[tid] = b_ih1[tid] + b_hh1[tid];
        bias2[tid] = b_ih2[tid] + b_hh2[tid];
        wz[tid]    = w_ih2[tid];
    }
    if (tid < 512) fcw[tid] = fc_w[tid];
    if (tid < NP) fcb[tid] = fc_b[tid];
    for (int i = tid; i < BM * NT; i += NTHR) {
        int t = i / BM, m = i % BM;
        int seq = seq0 + m;
        float z = 0.f;
        if (seq < NSEQ) {
            int b = seq / N_NODES, n = seq - b * N_NODES;
            z = zeta[(size_t)(b * NT + t) * N_NODES + n];
        }
        zs[m * NT + t] = z;
    }
    for (int i = tid; i < H * SP; i += NTHR) state[i] = 0.f;
    __syncthreads();

    float c1[8][2];
#pragma unroll
    for (int im = 0; im < 8; ++im) { c1[im][0] = 0.f; c1[im][1] = 0.f; }

    // ======== LSTM 1 (K = 96) ========
    for (int t = 0; t < NT; ++t) {
        {   // stage x_t into rows 64..95 (transposed)
            int kx = tid & 31;
            int m0 = tid >> 5;
#pragma unroll
            for (int j = 0; j < 8; ++j) {
                int m = m0 + 17 * j;
                state[(H + kx) * SP + m] =
                    g_seq[(size_t)(seq0 + m) * (NT * HG) + t * HG + kx];
            }
        }
        __syncthreads();

        ull acc[8][4];
        {
            const ull* bp = (const ull*)(bias1 + 2 * tg);
            ull b0 = bp[0], b1 = bp[32], b2 = bp[64], b3 = bp[96];
#pragma unroll
            for (int im = 0; im < 8; ++im) {
                acc[im][0] = b0; acc[im][1] = b1; acc[im][2] = b2; acc[im][3] = b3;
            }
        }

#pragma unroll 4
        for (int k = 0; k < K1; ++k) {
            const float* srow = state + k * SP + 8 * tm;
            float4 h0 = *(const float4*)(srow);
            float4 h1 = *(const float4*)(srow + 4);
            const ull* wr = (const ull*)(wbuf + (k << 8) + 2 * tg);
            ull wa = wr[0], wb = wr[32], wc = wr[64], wd = wr[96];
            float hv[8] = {h0.x, h0.y, h0.z, h0.w, h1.x, h1.y, h1.z, h1.w};
#pragma unroll
            for (int im = 0; im < 8; ++im) {
                ull hd = dup2(hv[im]);
                fma2(acc[im][0], hd, wa);
                fma2(acc[im][1], hd, wb);
                fma2(acc[im][2], hd, wc);
                fma2(acc[im][3], hd, wd);
            }
        }
        __syncthreads();
#pragma unroll
        for (int im = 0; im < 8; ++im) {
            float iv[2], fv[2], gv[2], ov[2];
            unpk(iv[0], iv[1], acc[im][0]);
            unpk(fv[0], fv[1], acc[im][1]);
            unpk(gv[0], gv[1], acc[im][2]);
            unpk(ov[0], ov[1], acc[im][3]);
#pragma unroll
            for (int r = 0; r < 2; ++r) {
                float ig = sigf(iv[r]);
                float fg = sigf(fv[r]);
                float gg = tanh_f(gv[r]);
                float og = sigf(ov[r]);
                float c = fmaf(fg, c1[im][r], ig * gg);
                c1[im][r] = c;
                state[(2 * tg + r) * SP + 8 * tm + im] = og * tanh_f(c);
            }
        }
        __syncthreads();
    }

    // ======== FC half 1 (reads final h1 in state) ========
    {
        int p = tid / BM;      // 544 = 4*136
        int m = tid - p * BM;
        float s = fcb[p];
#pragma unroll 8
        for (int k = 0; k < H; ++k) s = fmaf(state[k * SP + m], fcw[p * 128 + k], s);
        y1[p * BM + m] = s;
    }
    __syncthreads();

    // reload weight buffer rows 0..63 with w_hh2^T; zero h state
    for (int i = tid; i < H * G; i += NTHR) {
        int k = i >> 8, g = i & 255;
        wbuf[i] = w_hh2[g * H + k];
    }
    for (int i = tid; i < H * SP; i += NTHR) state[i] = 0.f;
    __syncthreads();

    float c2[8][2];
#pragma unroll
    for (int im = 0; im < 8; ++im) { c2[im][0] = 0.f; c2[im][1] = 0.f; }

    // ======== LSTM 2 (K = 64, scalar input folded into init) ========
    for (int t = 0; t < NT; ++t) {
        ull acc[8][4];
        {
            const ull* bp = (const ull*)(bias2 + 2 * tg);
            const ull* wp = (const ull*)(wz + 2 * tg);
            ull b0 = bp[0], b1 = bp[32], b2 = bp[64], b3 = bp[96];
            ull z0 = wp[0], z1 = wp[32], z2 = wp[64], z3 = wp[96];
#pragma unroll
            for (int im = 0; im < 8; ++im) {
                ull zd = dup2(zs[(8 * tm + im) * NT + t]);
                acc[im][0] = b0; fma2(acc[im][0], zd, z0);
                acc[im][1] = b1; fma2(acc[im][1], zd, z1);
                acc[im][2] = b2; fma2(acc[im][2], zd, z2);
                acc[im][3] = b3; fma2(acc[im][3], zd, z3);
            }
        }
#pragma unroll 4
        for (int k = 0; k < H; ++k) {
            const float* srow = state + k * SP + 8 * tm;
            float4 h0 = *(const float4*)(srow);
            float4 h1 = *(const float4*)(srow + 4);
            const ull* wr = (const ull*)(wbuf + (k << 8) + 2 * tg);
            ull wa = wr[0], wb = wr[32], wc = wr[64], wd = wr[96];
            float hv[8] = {h0.x, h0.y, h0.z, h0.w, h1.x, h1.y, h1.z, h1.w};
#pragma unroll
            for (int im = 0; im < 8; ++im) {
                ull hd = dup2(hv[im]);
                fma2(acc[im][0], hd, wa);
                fma2(acc[im][1], hd, wb);
                fma2(acc[im][2], hd, wc);
                fma2(acc[im][3], hd, wd);
            }
        }
        __syncthreads();
#pragma unroll
        for (int im = 0; im < 8; ++im) {
            float iv[2], fv[2], gv[2], ov[2];
            unpk(iv[0], iv[1], acc[im][0]);
            unpk(fv[0], fv[1], acc[im][1]);
            unpk(gv[0], gv[1], acc[im][2]);
            unpk(ov[0], ov[1], acc[im][3]);
#pragma unroll
            for (int r = 0; r < 2; ++r) {
                float ig = sigf(iv[r]);
                float fg = sigf(fv[r]);
                float gg = tanh_f(gv[r]);
                float og = sigf(ov[r]);
                float c = fmaf(fg, c2[im][r], ig * gg);
                c2[im][r] = c;
                state[(2 * tg + r) * SP + 8 * tm + im] = og * tanh_f(c);
            }
        }
        __syncthreads();
    }

    // ======== FC half 2 + transposed output write ========
    {
        int p = tid / BM;
        int m = tid - p * BM;
        float s = y1[p * BM + m];
#pragma unroll 8
        for (int k = 0; k < H; ++k) s = fmaf(state[k * SP + m], fcw[p * 128 + H + k], s);
        int seq = seq0 + m;
        if (seq < NSEQ) {
            int b = seq / N_NODES, n = seq - b * N_NODES;
            out[(size_t)(b * NP + p) * N_NODES + n] = s;
        }
    }
}

extern "C" void kernel_launch(void* const* d_in, const int* in_sizes, int n_in,
                              void* d_out, int out_size) {
    const float* era5  = (const float*)d_in[0];
    const float* zeta  = (const float*)d_in[1];
    const int*   ei    = (const int*)d_in[2];
    const float* gcn_w = (const float*)d_in[3];
    const float* gcn_b = (const float*)d_in[4];
    const float* w_ih1 = (const float*)d_in[5];
    const float* w_hh1 = (const float*)d_in[6];
    const float* b_ih1 = (const float*)d_in[7];
    const float* b_hh1 = (const float*)d_in[8];
    const float* w_ih2 = (const float*)d_in[9];
    const float* w_hh2 = (const float*)d_in[10];
    const float* b_ih2 = (const float*)d_in[11];
    const float* b_hh2 = (const float*)d_in[12];
    const float* fc_w  = (const float*)d_in[13];
    const float* fc_b  = (const float*)d_in[14];
    float* out = (float*)d_out;

    k_initdeg<<<(N_NODES + 255) / 256, 256>>>();
    k_degcount<<<(N_EDGES + 255) / 256, 256>>>(ei);
    k_scan<<<1, 1024>>>();
    k_fill<<<(N_EDGES + 255) / 256, 256>>>(ei);
    k_xw<<<(BT * N_NODES * HG + 255) / 256, 256>>>(era5, gcn_w);
    k_gather<<<(N_NODES * 32 + 255) / 256, 256>>>(gcn_b);

    size_t smem = (size_t)SMEM_FLOATS * sizeof(float);
    cudaFuncSetAttribute(k_lstm, cudaFuncAttributeMaxDynamicSharedMemorySize, (int)smem);
    k_lstm<<<(NSEQ + BM - 1) / BM, NTHR, smem>>>(
        zeta, w_ih1, w_hh1, b_ih1, b_hh1,
        w_ih2, w_hh2, b_ih2, b_hh2, fc_w, fc_b, out);
}

// round 4
// speedup vs baseline: 1.3974x; 1.1186x over previous
#include <cuda_runtime.h>

#define N_NODES 10000
#define N_EDGES 160000
#define NB 2
#define NT 12
#define NF 16
#define HG 32
#define H 64
#define G 256   /* 4H */
#define NP 4
#define NSEQ 20000
#define NSEQ_PAD 20160
#define BT 24

#define BM 136
#define NTHR 512
#define SP 140   /* MUST be divisible by 4: float4 loads at state + k*SP */
#define K1 96

// smem layout (floats)
#define OFF_WBUF  0
#define OFF_B1    24576
#define OFF_B2    24832
#define OFF_WZ    25088
#define OFF_FCW   25344
#define OFF_FCB   25856
#define OFF_ZS    25864            /* 136*12 = 1632 */
#define OFF_Y1    27496            /* 544 */
#define OFF_STATE 28040            /* 96*140 = 13440 */
#define SMEM_FLOATS (OFF_STATE + K1 * SP)

typedef unsigned long long ull;

__device__ __forceinline__ void fma2(ull& d, ull a, ull b) {
    asm("fma.rn.f32x2 %0, %1, %2, %0;" : "+l"(d) : "l"(a), "l"(b));
}
__device__ __forceinline__ ull dup2(float v) {
    ull r; unsigned u = __float_as_uint(v);
    asm("mov.b64 %0, {%1, %1};" : "=l"(r) : "r"(u));
    return r;
}
__device__ __forceinline__ void unpk(float& lo, float& hi, ull v) {
    unsigned a, b;
    asm("mov.b64 {%0, %1}, %2;" : "=r"(a), "=r"(b) : "l"(v));
    lo = __uint_as_float(a); hi = __uint_as_float(b);
}
__device__ __forceinline__ float tanha(float x) {
    float r; asm("tanh.approx.f32 %0, %1;" : "=f"(r) : "f"(x)); return r;
}
__device__ __forceinline__ float siga(float x) {
    return fmaf(tanha(0.5f * x), 0.5f, 0.5f);
}

// -------- device scratch (zero-initialized; pad region stays zero) --------
__device__ float g_xw[BT * N_NODES * HG];
__device__ float g_seq[NSEQ_PAD * NT * HG];
__device__ int   g_deg[N_NODES];
__device__ int   g_rowptr[N_NODES + 1];
__device__ int   g_cursor[N_NODES];
__device__ int   g_csrc[N_EDGES];
__device__ float g_dinv[N_NODES];

// ---------------- GCN: CSR build ----------------
__global__ void k_initdeg() {
    int i = blockIdx.x * blockDim.x + threadIdx.x;
    if (i < N_NODES) g_deg[i] = 0;
}

__global__ void k_degcount(const int* __restrict__ ei) {
    int e = blockIdx.x * blockDim.x + threadIdx.x;
    if (e < N_EDGES) atomicAdd(&g_deg[ei[N_EDGES + e]], 1);
}

__global__ void k_scan() {
    __shared__ int part[1024];
    const int CH = 10;
    int tid = threadIdx.x;
    int base = tid * CH;
    int loc[CH];
    int s = 0;
#pragma unroll
    for (int j = 0; j < CH; ++j) {
        int idx = base + j;
        int v = (idx < N_NODES) ? g_deg[idx] : 0;
        loc[j] = s; s += v;
    }
    part[tid] = s;
    __syncthreads();
    for (int off = 1; off < 1024; off <<= 1) {
        int v = (tid >= off) ? part[tid - off] : 0;
        __syncthreads();
        part[tid] += v;
        __syncthreads();
    }
    int boff = (tid > 0) ? part[tid - 1] : 0;
#pragma unroll
    for (int j = 0; j < CH; ++j) {
        int idx = base + j;
        if (idx < N_NODES) {
            int rp = boff + loc[j];
            g_rowptr[idx] = rp;
            g_cursor[idx] = rp;
            g_dinv[idx]   = rsqrtf((float)(g_deg[idx] + 1));
        }
    }
    if (tid == 1023) g_rowptr[N_NODES] = part[1023];
}

__global__ void k_fill(const int* __restrict__ ei) {
    int e = blockIdx.x * blockDim.x + threadIdx.x;
    if (e < N_EDGES) {
        int d = ei[N_EDGES + e];
        int p = atomicAdd(&g_cursor[d], 1);
        g_csrc[p] = ei[e];
    }
}

// ---------------- GCN: x @ W ----------------
__global__ void k_xw(const float* __restrict__ x, const float* __restrict__ w) {
    __shared__ float ws[NF * HG];
    for (int i = threadIdx.x; i < NF * HG; i += blockDim.x) ws[i] = w[i];
    __syncthreads();
    int idx = blockIdx.x * blockDim.x + threadIdx.x;
    if (idx >= BT * N_NODES * HG) return;
    int row = idx >> 5;
    int c = idx & 31;
    const float* xr = x + (size_t)row * NF;
    float s = 0.f;
#pragma unroll
    for (int f = 0; f < NF; ++f) s = fmaf(__ldg(&xr[f]), ws[f * HG + c], s);
    g_xw[idx] = s;
}

// ---------------- GCN: per-node gather ----------------
__global__ void k_gather(const float* __restrict__ gcn_b) {
    int gw = (blockIdx.x * blockDim.x + threadIdx.x) >> 5;
    int c = threadIdx.x & 31;
    if (gw >= N_NODES) return;
    int n = gw;
    float dn = g_dinv[n];
    float acc[BT];
#pragma unroll
    for (int bt = 0; bt < BT; ++bt)
        acc[bt] = dn * g_xw[(size_t)(bt * N_NODES + n) * HG + c];
    int e0 = g_rowptr[n], e1 = g_rowptr[n + 1];
    for (int e = e0; e < e1; ++e) {
        int s = g_csrc[e];
        float ds = g_dinv[s];
        const float* xp = g_xw + (size_t)s * HG + c;
#pragma unroll
        for (int bt = 0; bt < BT; ++bt)
            acc[bt] = fmaf(ds, xp[(size_t)bt * N_NODES * HG], acc[bt]);
    }
    float bc = gcn_b[c];
#pragma unroll
    for (int bt = 0; bt < BT; ++bt) {
        int b = bt / NT, t = bt % NT;
        g_seq[((size_t)(b * N_NODES + n) * NT + t) * HG + c] = fmaf(dn, acc[bt], bc);
    }
}

// ---------------- fused LSTM1 + LSTM2 + FC ----------------
// 512 threads, 16 warps (4/4/4/4 per SMSP). Main tile: warp tm owns m in
// [8tm, 8tm+8). Warps tm<8 additionally own m_e = 128+tm (extra column).
__global__ void __launch_bounds__(NTHR, 1)
k_lstm(const float* __restrict__ zeta,
       const float* __restrict__ w_ih1, const float* __restrict__ w_hh1,
       const float* __restrict__ b_ih1, const float* __restrict__ b_hh1,
       const float* __restrict__ w_ih2, const float* __restrict__ w_hh2,
       const float* __restrict__ b_ih2, const float* __restrict__ b_hh2,
       const float* __restrict__ fc_w, const float* __restrict__ fc_b,
       float* __restrict__ out) {
    extern __shared__ float smf[];
    float* wbuf  = smf + OFF_WBUF;
    float* bias1 = smf + OFF_B1;
    float* bias2 = smf + OFF_B2;
    float* wz    = smf + OFF_WZ;
    float* fcw   = smf + OFF_FCW;
    float* fcb   = smf + OFF_FCB;
    float* zs    = smf + OFF_ZS;
    float* y1    = smf + OFF_Y1;
    float* state = smf + OFF_STATE;   // [96][SP]: rows 0..63 h, 64..95 x_t

    int tid = threadIdx.x;
    int tg = tid & 31, tm = tid >> 5;           // tm in [0,16)
    bool xw_extra = (tm < 8);
    int me = 128 + tm;                          // extra m (valid if xw_extra)
    int seq0 = blockIdx.x * BM;

    for (int i = tid; i < K1 * G; i += NTHR) {
        int k = i >> 8, g = i & 255;
        wbuf[i] = (k < H) ? w_hh1[g * H + k] : w_ih1[g * HG + (k - H)];
    }
    if (tid < G) {
        bias1[tid] = b_ih1[tid] + b_hh1[tid];
        bias2[tid] = b_ih2[tid] + b_hh2[tid];
        wz[tid]    = w_ih2[tid];
    }
    if (tid < 512) fcw[tid] = fc_w[tid];
    if (tid < NP) fcb[tid] = fc_b[tid];
    for (int i = tid; i < BM * NT; i += NTHR) {
        int t = i / BM, m = i % BM;
        int seq = seq0 + m;
        float z = 0.f;
        if (seq < NSEQ) {
            int b = seq / N_NODES, n = seq - b * N_NODES;
            z = zeta[(size_t)(b * NT + t) * N_NODES + n];
        }
        zs[m * NT + t] = z;
    }
    for (int i = tid; i < H * SP; i += NTHR) state[i] = 0.f;
    __syncthreads();

    float c1[8][2], c1e[2];
#pragma unroll
    for (int im = 0; im < 8; ++im) { c1[im][0] = 0.f; c1[im][1] = 0.f; }
    c1e[0] = 0.f; c1e[1] = 0.f;

    // ======== LSTM 1 (K = 96) ========
    for (int t = 0; t < NT; ++t) {
        // stage x_t into rows 64..95
        for (int i = tid; i < 32 * BM; i += NTHR) {
            int kx = i & 31, m = i >> 5;
            state[(H + kx) * SP + m] =
                g_seq[(size_t)(seq0 + m) * (NT * HG) + t * HG + kx];
        }
        __syncthreads();

        ull acc[8][4], acce[4];
        {
            const ull* bp = (const ull*)(bias1 + 2 * tg);
            ull b0 = bp[0], b1 = bp[32], b2 = bp[64], b3 = bp[96];
#pragma unroll
            for (int im = 0; im < 8; ++im) {
                acc[im][0] = b0; acc[im][1] = b1; acc[im][2] = b2; acc[im][3] = b3;
            }
            acce[0] = b0; acce[1] = b1; acce[2] = b2; acce[3] = b3;
        }

#pragma unroll 4
        for (int k = 0; k < K1; ++k) {
            const float* srow = state + k * SP + 8 * tm;
            float4 h0 = *(const float4*)(srow);
            float4 h1 = *(const float4*)(srow + 4);
            const ull* wr = (const ull*)(wbuf + (k << 8) + 2 * tg);
            ull wa = wr[0], wb = wr[32], wc = wr[64], wd = wr[96];
            float hv[8] = {h0.x, h0.y, h0.z, h0.w, h1.x, h1.y, h1.z, h1.w};
#pragma unroll
            for (int im = 0; im < 8; ++im) {
                ull hd = dup2(hv[im]);
                fma2(acc[im][0], hd, wa);
                fma2(acc[im][1], hd, wb);
                fma2(acc[im][2], hd, wc);
                fma2(acc[im][3], hd, wd);
            }
            if (xw_extra) {
                ull hd = dup2(state[k * SP + me]);
                fma2(acce[0], hd, wa);
                fma2(acce[1], hd, wb);
                fma2(acce[2], hd, wc);
                fma2(acce[3], hd, wd);
            }
        }
        __syncthreads();
#pragma unroll
        for (int im = 0; im < 8; ++im) {
            float iv[2], fv[2], gv[2], ov[2];
            unpk(iv[0], iv[1], acc[im][0]);
            unpk(fv[0], fv[1], acc[im][1]);
            unpk(gv[0], gv[1], acc[im][2]);
            unpk(ov[0], ov[1], acc[im][3]);
#pragma unroll
            for (int r = 0; r < 2; ++r) {
                float c = fmaf(siga(fv[r]), c1[im][r], siga(iv[r]) * tanha(gv[r]));
                c1[im][r] = c;
                state[(2 * tg + r) * SP + 8 * tm + im] = siga(ov[r]) * tanha(c);
            }
        }
        if (xw_extra) {
            float iv[2], fv[2], gv[2], ov[2];
            unpk(iv[0], iv[1], acce[0]);
            unpk(fv[0], fv[1], acce[1]);
            unpk(gv[0], gv[1], acce[2]);
            unpk(ov[0], ov[1], acce[3]);
#pragma unroll
            for (int r = 0; r < 2; ++r) {
                float c = fmaf(siga(fv[r]), c1e[r], siga(iv[r]) * tanha(gv[r]));
                c1e[r] = c;
                state[(2 * tg + r) * SP + me] = siga(ov[r]) * tanha(c);
            }
        }
        __syncthreads();
    }

    // ======== FC half 1 ========
    for (int idx = tid; idx < NP * BM; idx += NTHR) {
        int p = idx / BM, m = idx - p * BM;
        float s = fcb[p];
#pragma unroll 8
        for (int k = 0; k < H; ++k) s = fmaf(state[k * SP + m], fcw[p * 128 + k], s);
        y1[p * BM + m] = s;
    }
    __syncthreads();

    // reload weight rows 0..63 with w_hh2^T; zero h state
    for (int i = tid; i < H * G; i += NTHR) {
        int k = i >> 8, g = i & 255;
        wbuf[i] = w_hh2[g * H + k];
    }
    for (int i = tid; i < H * SP; i += NTHR) state[i] = 0.f;
    __syncthreads();

    float c2[8][2], c2e[2];
#pragma unroll
    for (int im = 0; im < 8; ++im) { c2[im][0] = 0.f; c2[im][1] = 0.f; }
    c2e[0] = 0.f; c2e[1] = 0.f;

    // ======== LSTM 2 (K = 64) ========
    for (int t = 0; t < NT; ++t) {
        ull acc[8][4], acce[4];
        {
            const ull* bp = (const ull*)(bias2 + 2 * tg);
            const ull* wp = (const ull*)(wz + 2 * tg);
            ull b0 = bp[0], b1 = bp[32], b2 = bp[64], b3 = bp[96];
            ull z0 = wp[0], z1 = wp[32], z2 = wp[64], z3 = wp[96];
#pragma unroll
            for (int im = 0; im < 8; ++im) {
                ull zd = dup2(zs[(8 * tm + im) * NT + t]);
                acc[im][0] = b0; fma2(acc[im][0], zd, z0);
                acc[im][1] = b1; fma2(acc[im][1], zd, z1);
                acc[im][2] = b2; fma2(acc[im][2], zd, z2);
                acc[im][3] = b3; fma2(acc[im][3], zd, z3);
            }
            ull zd = dup2(xw_extra ? zs[me * NT + t] : 0.f);
            acce[0] = b0; fma2(acce[0], zd, z0);
            acce[1] = b1; fma2(acce[1], zd, z1);
            acce[2] = b2; fma2(acce[2], zd, z2);
            acce[3] = b3; fma2(acce[3], zd, z3);
        }
#pragma unroll 4
        for (int k = 0; k < H; ++k) {
            const float* srow = state + k * SP + 8 * tm;
            float4 h0 = *(const float4*)(srow);
            float4 h1 = *(const float4*)(srow + 4);
            const ull* wr = (const ull*)(wbuf + (k << 8) + 2 * tg);
            ull wa = wr[0], wb = wr[32], wc = wr[64], wd = wr[96];
            float hv[8] = {h0.x, h0.y, h0.z, h0.w, h1.x, h1.y, h1.z, h1.w};
#pragma unroll
            for (int im = 0; im < 8; ++im) {
                ull hd = dup2(hv[im]);
                fma2(acc[im][0], hd, wa);
                fma2(acc[im][1], hd, wb);
                fma2(acc[im][2], hd, wc);
                fma2(acc[im][3], hd, wd);
            }
            if (xw_extra) {
                ull hd = dup2(state[k * SP + me]);
                fma2(acce[0], hd, wa);
                fma2(acce[1], hd, wb);
                fma2(acce[2], hd, wc);
                fma2(acce[3], hd, wd);
            }
        }
        __syncthreads();
#pragma unroll
        for (int im = 0; im < 8; ++im) {
            float iv[2], fv[2], gv[2], ov[2];
            unpk(iv[0], iv[1], acc[im][0]);
            unpk(fv[0], fv[1], acc[im][1]);
            unpk(gv[0], gv[1], acc[im][2]);
            unpk(ov[0], ov[1], acc[im][3]);
#pragma unroll
            for (int r = 0; r < 2; ++r) {
                float c = fmaf(siga(fv[r]), c2[im][r], siga(iv[r]) * tanha(gv[r]));
                c2[im][r] = c;
                state[(2 * tg + r) * SP + 8 * tm + im] = siga(ov[r]) * tanha(c);
            }
        }
        if (xw_extra) {
            float iv[2], fv[2], gv[2], ov[2];
            unpk(iv[0], iv[1], acce[0]);
            unpk(fv[0], fv[1], acce[1]);
            unpk(gv[0], gv[1], acce[2]);
            unpk(ov[0], ov[1], acce[3]);
#pragma unroll
            for (int r = 0; r < 2; ++r) {
                float c = fmaf(siga(fv[r]), c2e[r], siga(iv[r]) * tanha(gv[r]));
                c2e[r] = c;
                state[(2 * tg + r) * SP + me] = siga(ov[r]) * tanha(c);
            }
        }
        __syncthreads();
    }

    // ======== FC half 2 + transposed output write ========
    for (int idx = tid; idx < NP * BM; idx += NTHR) {
        int p = idx / BM, m = idx - p * BM;
        float s = y1[p * BM + m];
#pragma unroll 8
        for (int k = 0; k < H; ++k) s = fmaf(state[k * SP + m], fcw[p * 128 + H + k], s);
        int seq = seq0 + m;
        if (seq < NSEQ) {
            int b = seq / N_NODES, n = seq - b * N_NODES;
            out[(size_t)(b * NP + p) * N_NODES + n] = s;
        }
    }
}

extern "C" void kernel_launch(void* const* d_in, const int* in_sizes, int n_in,
                              void* d_out, int out_size) {
    const float* era5  = (const float*)d_in[0];
    const float* zeta  = (const float*)d_in[1];
    const int*   ei    = (const int*)d_in[2];
    const float* gcn_w = (const float*)d_in[3];
    const float* gcn_b = (const float*)d_in[4];
    const float* w_ih1 = (const float*)d_in[5];
    const float* w_hh1 = (const float*)d_in[6];
    const float* b_ih1 = (const float*)d_in[7];
    const float* b_hh1 = (const float*)d_in[8];
    const float* w_ih2 = (const float*)d_in[9];
    const float* w_hh2 = (const float*)d_in[10];
    const float* b_ih2 = (const float*)d_in[11];
    const float* b_hh2 = (const float*)d_in[12];
    const float* fc_w  = (const float*)d_in[13];
    const float* fc_b  = (const float*)d_in[14];
    float* out = (float*)d_out;

    k_initdeg<<<(N_NODES + 255) / 256, 256>>>();
    k_degcount<<<(N_EDGES + 255) / 256, 256>>>(ei);
    k_scan<<<1, 1024>>>();
    k_fill<<<(N_EDGES + 255) / 256, 256>>>(ei);
    k_xw<<<(BT * N_NODES * HG + 255) / 256, 256>>>(era5, gcn_w);
    k_gather<<<(N_NODES * 32 + 255) / 256, 256>>>(gcn_b);

    size_t smem = (size_t)SMEM_FLOATS * sizeof(float);
    cudaFuncSetAttribute(k_lstm, cudaFuncAttributeMaxDynamicSharedMemorySize, (int)smem);
    k_lstm<<<(NSEQ + BM - 1) / BM, NTHR, smem>>>(
        zeta, w_ih1, w_hh1, b_ih1, b_hh1,
        w_ih2, w_hh2, b_ih2, b_hh2, fc_w, fc_b, out);
}